// round 15
// baseline (speedup 1.0000x reference)
#include <cuda_runtime.h>
#include <cuda_bf16.h>
#include <cuda_fp16.h>
#include <cstdint>

// Problem constants
#define Nn   400000
#define Hh   256
#define Cc   128
#define Aa   32
#define Gg   512
#define NGg  1024
#define CpA  (Cc + Aa)          // 160
#define BN_EPS 1e-5f

#define Kt   512                // concat K: [init | fin]
#define Nt   256                // outputs: [gate(128) | t(128)]
#define Mt   64                 // nodes per block (2 CTAs/SM)
#define KC   64                 // K chunk
#define AROW (KC + 8)           // padded smem row, elems (72)
#define NTHR 256                // 8 warps: 2 row-groups x 4 col-groups

// ---------------- scratch (no allocations allowed) ----------------
__device__ float g_readout[NGg * Cc];            // segment sums  [1024,128]
__device__ float g_scale[CpA];
__device__ float g_shift[CpA];
__device__ float g_hidden[NGg * Gg];
__device__ __align__(16) __half g_Bh[Nt * Kt];   // combined weights [n][k], fp16

// ---------------- PTX helpers ----------------
__device__ __forceinline__ uint32_t smem_u32(const void* p) {
    uint32_t a;
    asm("{ .reg .u64 t; cvta.to.shared.u64 t, %1; cvt.u32.u64 %0, t; }" : "=r"(a) : "l"(p));
    return a;
}
#define LDSM4(r, addr)                                                        \
    asm volatile("ldmatrix.sync.aligned.m8n8.x4.shared.b16 {%0,%1,%2,%3}, [%4];" \
        : "=r"((r)[0]), "=r"((r)[1]), "=r"((r)[2]), "=r"((r)[3]) : "r"(addr))

#define MMA(d, a, b0, b1)                                                     \
    asm volatile("mma.sync.aligned.m16n8k16.row.col.f32.f16.f16.f32 "         \
        "{%0,%1,%2,%3},{%4,%5,%6,%7},{%8,%9},{%0,%1,%2,%3};"                  \
        : "+f"((d)[0]), "+f"((d)[1]), "+f"((d)[2]), "+f"((d)[3])              \
        : "r"((a)[0]), "r"((a)[1]), "r"((a)[2]), "r"((a)[3]), "r"(b0), "r"(b1))

#define CP16(dst, src)                                                        \
    asm volatile("cp.async.cg.shared.global [%0], [%1], 16;" :: "r"(dst), "l"(src) : "memory")
#define CP_COMMIT() asm volatile("cp.async.commit_group;" ::: "memory")
#define CP_WAIT0()  asm volatile("cp.async.wait_group 0;" ::: "memory")

// ---------------- packed f32x2 helpers (MLP tail kernels) ----------------
__device__ __forceinline__ unsigned long long pack2(float lo, float hi) {
    unsigned long long r;
    asm("mov.b64 %0, {%1, %2};" : "=l"(r) : "f"(lo), "f"(hi));
    return r;
}
__device__ __forceinline__ void unpack2(unsigned long long v, float& lo, float& hi) {
    asm("mov.b64 {%0, %1}, %2;" : "=f"(lo), "=f"(hi) : "l"(v));
}
__device__ __forceinline__ unsigned long long fma2(unsigned long long a,
                                                   unsigned long long b,
                                                   unsigned long long c) {
    unsigned long long d;
    asm("fma.rn.f32x2 %0, %1, %2, %3;" : "=l"(d) : "l"(a), "l"(b), "l"(c));
    return d;
}

// ---------------- kernel: build combined fp16 weights + zero readout ----------------
// B[n][k]: n<128 -> Wg[k][n]; n>=128 -> (k>=256 ? Wt[k-256][n-128] : 0)
__global__ void prep_kernel(const float* __restrict__ Wg, const float* __restrict__ Wt) {
    int idx = blockIdx.x * 256 + threadIdx.x;     // 0 .. 131071
    int n = idx >> 9, k = idx & 511;
    float w;
    if (n < 128)          w = Wg[(size_t)k * Cc + n];
    else if (k >= 256)    w = Wt[(size_t)(k - 256) * Cc + (n - 128)];
    else                  w = 0.0f;
    g_Bh[idx] = __float2half_rn(w);
    g_readout[idx] = 0.0f;
}

// ---------------- node kernel: HMMA GEMM + gate + segment-sum ----------------
// dynamic smem, 2 stages of:
//   A [64][72] fp16 (9216B) | B [256][72] fp16 (36864B)   = 46080B/stage
// 92160B/CTA -> 2 CTAs per SM
#define OFF_B     9216
#define STG       46080
#define SMEM_DYN  (2 * STG)      // 92160
#define OUTROW    132            // fp32 out tile row stride (elems)

__device__ __forceinline__ void ldgA(const float* __restrict__ X, int nodeBase,
                                     int kloc, int tid, float4* aR) {
#pragma unroll
    for (int it = 0; it < 4; ++it) {
        int f = tid + it * NTHR;
        int m = f >> 4, q = f & 15;
        aR[it] = *(const float4*)(X + (size_t)(nodeBase + m) * Hh + kloc + 4 * q);
    }
}

__device__ __forceinline__ void stsA(char* stage, int tid, const float4* aR) {
#pragma unroll
    for (int it = 0; it < 4; ++it) {
        int f = tid + it * NTHR;
        int m = f >> 4, q = f & 15;
        float4 v = aR[it];
        __half2 h0 = __floats2half2_rn(v.x, v.y);
        __half2 h1 = __floats2half2_rn(v.z, v.w);
        uint32_t off = m * (AROW * 2) + q * 8;
        uint2 H; H.x = *(uint32_t*)&h0; H.y = *(uint32_t*)&h1;
        *(uint2*)(stage + off) = H;
    }
}

// copy B rows [0, nrows) for one K chunk; nrows is 128 (gate-only) or 256
__device__ __forceinline__ void cpB(uint32_t stB, int kbytes, int tid, int nrows) {
    const int iters = nrows >> 5;                // 4 or 8
    for (int it = 0; it < iters; ++it) {
        int f = tid + it * NTHR;
        int n = f >> 3, q = f & 7;
        uint32_t dst = n * (AROW * 2) + q * 16;
        CP16(stB + dst, (const char*)g_Bh + (size_t)n * (Kt * 2) + kbytes + q * 16);
    }
    CP_COMMIT();
}

__global__ __launch_bounds__(NTHR, 2)
void node_kernel(const float* __restrict__ xinit, const float* __restrict__ xfin,
                 const int* __restrict__ gids,
                 const float* __restrict__ bg, const float* __restrict__ bt) {
    extern __shared__ char smem[];
    __shared__ int s_gid[Mt];
    const uint32_t sbase = smem_u32(smem);
    const int tid = threadIdx.x;
    const int wid = tid >> 5;
    const int l = tid & 31;
    const int wm = wid & 1;          // 0..1 -> 32 rows each
    const int wn = wid >> 1;         // 0..3 -> 32-col gate slice AND 32-col t slice
    const int nodeBase = blockIdx.x * Mt;

    if (tid < Mt) s_gid[tid] = gids[nodeBase + tid];

    // ldmatrix per-thread offsets (bytes)
    const uint32_t aOff = ((wm * 32 + (l & 15)) * AROW + ((l >> 4) * 8)) * 2;
    // B col-slice bases: gate slice at cols [wn*32, wn*32+32),
    //                    t slice at cols [128 + wn*32, 128 + wn*32 + 32)
    const uint32_t bRowSel = (((l >> 4) & 1) * 8 + (l & 7));
    const uint32_t bKSel = ((l >> 3) & 1) * 8;
    const uint32_t bOffG = ((wn * 32 + bRowSel) * AROW + bKSel) * 2 + OFF_B;
    const uint32_t bOffT = (((128 + wn * 32) + bRowSel) * AROW + bKSel) * 2 + OFF_B;

    float accG[2][4][4];             // gate: [mt 16-row][nt 8-col][frag]
    float accT[2][4][4];             // t
#pragma unroll
    for (int i = 0; i < 2; i++)
#pragma unroll
        for (int j = 0; j < 4; j++)
#pragma unroll
            for (int p = 0; p < 4; p++) { accG[i][j][p] = 0.0f; accT[i][j][p] = 0.0f; }

    float4 rA[4];

    // prologue: chunk 0 staged (init half, gate-only B rows)
    ldgA(xinit, nodeBase, 0, tid, rA);
    cpB(sbase + OFF_B, 0, tid, 128);
    stsA(smem, tid, rA);
    CP_WAIT0();
    __syncthreads();

    for (int j = 0; j < 8; ++j) {
        const uint32_t stg = sbase + (uint32_t)(j & 1) * STG;
        // prefetch chunk j+1 into the other stage
        if (j + 1 < 8) {
            const int c = j + 1;
            cpB(sbase + (uint32_t)(c & 1) * STG + OFF_B, c * KC * 2, tid,
                (c < 4) ? 128 : 256);
            const float* X = (c < 4) ? xinit : xfin;
            ldgA(X, nodeBase, (c & 3) * KC, tid, rA);
        }

        // all 8 warps: 32-col gate slice every chunk; 32-col t slice on chunks 4-7
        const bool doT = (j >= 4);
#pragma unroll
        for (int ks = 0; ks < 4; ++ks) {
            const uint32_t aA = stg + aOff + ks * 32;
            uint32_t ah0[4], ah1[4];
            LDSM4(ah0, aA);
            LDSM4(ah1, aA + 16 * AROW * 2);
#pragma unroll
            for (int np = 0; np < 2; ++np) {
                const uint32_t bA = stg + bOffG + np * (16 * AROW * 2) + ks * 32;
                uint32_t bh[4];
                LDSM4(bh, bA);
                MMA(accG[0][2 * np],     ah0, bh[0], bh[1]);
                MMA(accG[0][2 * np + 1], ah0, bh[2], bh[3]);
                MMA(accG[1][2 * np],     ah1, bh[0], bh[1]);
                MMA(accG[1][2 * np + 1], ah1, bh[2], bh[3]);
            }
            if (doT) {
#pragma unroll
                for (int np = 0; np < 2; ++np) {
                    const uint32_t bA = stg + bOffT + np * (16 * AROW * 2) + ks * 32;
                    uint32_t bh[4];
                    LDSM4(bh, bA);
                    MMA(accT[0][2 * np],     ah0, bh[0], bh[1]);
                    MMA(accT[0][2 * np + 1], ah0, bh[2], bh[3]);
                    MMA(accT[1][2 * np],     ah1, bh[0], bh[1]);
                    MMA(accT[1][2 * np + 1], ah1, bh[2], bh[3]);
                }
            }
        }

        // STS chunk j+1 (LDG'd at top of this iteration -> full MMA block of slack)
        if (j + 1 < 8) {
            stsA(smem + ((j + 1) & 1) * STG, tid, rA);
            CP_WAIT0();
        }
        __syncthreads();
    }

    // ---- epilogue: each warp owns matching gate & t columns -> no exchange ----
    float* sOut = (float*)smem;          // [64][OUTROW] fp32, aliases stages
    const int r = l >> 2;
    const int cq = (l & 3) * 2;

#pragma unroll
    for (int mt = 0; mt < 2; ++mt)
#pragma unroll
        for (int nt = 0; nt < 4; ++nt) {
            int m = wm * 32 + mt * 16 + r;
            int c = wn * 32 + nt * 8 + cq;
            float bg0 = bg[c], bg1 = bg[c + 1];
            float bt0 = bt[c], bt1 = bt[c + 1];
            float* p = sOut + m * OUTROW + c;
            p[0] = (accT[mt][nt][0] + bt0) / (1.0f + __expf(-(accG[mt][nt][0] + bg0)));
            p[1] = (accT[mt][nt][1] + bt1) / (1.0f + __expf(-(accG[mt][nt][1] + bg1)));
            p[8 * OUTROW]     = (accT[mt][nt][2] + bt0) / (1.0f + __expf(-(accG[mt][nt][2] + bg0)));
            p[8 * OUTROW + 1] = (accT[mt][nt][3] + bt1) / (1.0f + __expf(-(accG[mt][nt][3] + bg1)));
        }
    __syncthreads();

    // sorted-id run-length segment sum: 2 threads per channel, 32 nodes each
    {
        const int c = tid & 127;
        const int n0 = (tid >> 7) * 32;
        float run = 0.0f;
        int cur = s_gid[n0];
        for (int n = n0; n < n0 + 32; ++n) {
            int g = s_gid[n];
            if (g != cur) {
                atomicAdd(&g_readout[(size_t)cur * Cc + c], run);
                run = 0.0f; cur = g;
            }
            run += sOut[n * OUTROW + c];
        }
        atomicAdd(&g_readout[(size_t)cur * Cc + c], run);
    }
}

// ---------------- kernel: per-column BN stats -> scale/shift ----------------
__global__ __launch_bounds__(256)
void stats_kernel(const float* __restrict__ aux,
                  const float* __restrict__ gamma, const float* __restrict__ beta) {
    const int j = blockIdx.x;
    const int tid = threadIdx.x;
    float s = 0.0f, sq = 0.0f;
    for (int g = tid; g < NGg; g += 256) {
        float v = (j < Cc) ? g_readout[(size_t)g * Cc + j]
                           : aux[(size_t)g * Aa + (j - Cc)];
        s += v; sq += v * v;
    }
#pragma unroll
    for (int o = 16; o; o >>= 1) {
        s  += __shfl_xor_sync(0xffffffffu, s,  o);
        sq += __shfl_xor_sync(0xffffffffu, sq, o);
    }
    __shared__ float ws[8], wq[8];
    if ((tid & 31) == 0) { ws[tid >> 5] = s; wq[tid >> 5] = sq; }
    __syncthreads();
    if (tid == 0) {
        float S = 0.0f, Q = 0.0f;
#pragma unroll
        for (int i = 0; i < 8; i++) { S += ws[i]; Q += wq[i]; }
        float mean = S * (1.0f / NGg);
        float var  = Q * (1.0f / NGg) - mean * mean;
        float sc = gamma[j] * rsqrtf(var + BN_EPS);
        g_scale[j] = sc;
        g_shift[j] = beta[j] - mean * sc;
    }
}

// ---------------- kernel: hidden = relu(norm @ W1 + b1) ----------------
// 32x32 tile, grid (NGg/32, Gg/32) = (32, 16) = 512 CTAs
__global__ __launch_bounds__(256)
void mlp1_kernel(const float* __restrict__ aux,
                 const float* __restrict__ W1, const float* __restrict__ b1) {
    __shared__ float sA[32][33];
    __shared__ float sB[32][33];
    const int tid = threadIdx.x;
    const int tm = tid >> 4, tc = tid & 15;     // 16x16 threads: 2 rows x 2 cols each
    const int c0 = tc * 2;
    const int rowBase = blockIdx.x * 32;
    const int colBase = blockIdx.y * 32;

    unsigned long long acc[2] = {0ULL, 0ULL};

    for (int chunk = 0; chunk < 5; ++chunk) {       // K = 160
        const int k0 = chunk * 32;
        __syncthreads();
        {   // A tile 32x32, normalized on load: 256 float4 = 256 threads
            int n = tid >> 3, q = tid & 7;
            int j = k0 + 4 * q;
            float4 v;
            if (j < Cc) v = *(const float4*)(g_readout + (size_t)(rowBase + n) * Cc + j);
            else        v = *(const float4*)(aux + (size_t)(rowBase + n) * Aa + (j - Cc));
            float4 sc = *(const float4*)(g_scale + j);
            float4 sh = *(const float4*)(g_shift + j);
            sA[n][4 * q + 0] = fmaf(v.x, sc.x, sh.x);
            sA[n][4 * q + 1] = fmaf(v.y, sc.y, sh.y);
            sA[n][4 * q + 2] = fmaf(v.z, sc.z, sh.z);
            sA[n][4 * q + 3] = fmaf(v.w, sc.w, sh.w);
        }
        {   // B tile 32x32: 256 float4 = 1 per thread
            int k = tid >> 3, c4 = (tid & 7) * 4;
            float4 v = *(const float4*)(W1 + (size_t)(k0 + k) * Gg + colBase + c4);
            sB[k][c4 + 0] = v.x; sB[k][c4 + 1] = v.y;
            sB[k][c4 + 2] = v.z; sB[k][c4 + 3] = v.w;
        }
        __syncthreads();
#pragma unroll 8
        for (int k = 0; k < 32; ++k) {
            unsigned long long w = pack2(sB[k][c0], sB[k][c0 + 1]);
#pragma unroll
            for (int i = 0; i < 2; i++) {
                float a = sA[tm * 2 + i][k];
                acc[i] = fma2(pack2(a, a), w, acc[i]);
            }
        }
    }
    float b0 = b1[colBase + c0], b1v = b1[colBase + c0 + 1];
#pragma unroll
    for (int i = 0; i < 2; i++) {
        int r = rowBase + tm * 2 + i;
        float lo, hi; unpack2(acc[i], lo, hi);
        g_hidden[(size_t)r * Gg + colBase + c0]     = fmaxf(lo + b0, 0.0f);
        g_hidden[(size_t)r * Gg + colBase + c0 + 1] = fmaxf(hi + b1v, 0.0f);
    }
}

// ---------------- kernel: logits = hidden @ W2 + b2 ----------------
// 8-row tile, grid NGg/8 = 128 CTAs
__global__ __launch_bounds__(256)
void mlp2_kernel(const float* __restrict__ W2, const float* __restrict__ b2,
                 float* __restrict__ out) {
    __shared__ float sA[8][65];
    __shared__ float sB[64][128];
    const int tid = threadIdx.x;
    const int tm = tid >> 5, tc = tid & 31;     // 8 rows x 32 col-groups
    const int c0 = tc * 4;
    const int rowBase = blockIdx.x * 8;

    unsigned long long acc[2] = {0ULL, 0ULL};
    for (int chunk = 0; chunk < 8; ++chunk) {       // K = 512
        const int k0 = chunk * 64;
        __syncthreads();
        if (tid < 128) {                            // A tile 8x64 = 128 float4
            int n = tid >> 4, q = tid & 15;
            float4 v = *(const float4*)(g_hidden + (size_t)(rowBase + n) * Gg + k0 + 4 * q);
            sA[n][4 * q + 0] = v.x; sA[n][4 * q + 1] = v.y;
            sA[n][4 * q + 2] = v.z; sA[n][4 * q + 3] = v.w;
        }
#pragma unroll
        for (int it = 0; it < 8; ++it) {            // B tile 64x128
            int f = tid + it * 256;
            int k = f >> 5, c4 = (f & 31) * 4;
            *(float4*)&sB[k][c4] = *(const float4*)(W2 + (size_t)(k0 + k) * Cc + c4);
        }
        __syncthreads();
#pragma unroll 8
        for (int k = 0; k < 64; ++k) {
            float a = sA[tm][k];
            unsigned long long av = pack2(a, a);
            ulonglong2 w = *(const ulonglong2*)&sB[k][c0];
            acc[0] = fma2(av, w.x, acc[0]);
            acc[1] = fma2(av, w.y, acc[1]);
        }
    }
#pragma unroll
    for (int j = 0; j < 2; j++) {
        float lo, hi; unpack2(acc[j], lo, hi);
        int r = rowBase + tm;
        out[(size_t)r * Cc + c0 + 2 * j]     = lo + b2[c0 + 2 * j];
        out[(size_t)r * Cc + c0 + 2 * j + 1] = hi + b2[c0 + 2 * j + 1];
    }
}

// ---------------- launch ----------------
extern "C" void kernel_launch(void* const* d_in, const int* in_sizes, int n_in,
                              void* d_out, int out_size) {
    (void)in_sizes; (void)out_size;
    const float* xinit = (const float*)d_in[0];
    const float* xfin  = (const float*)d_in[1];
    const float* aux   = (const float*)d_in[2];
    const int*   gid   = (const int*)d_in[3];
    const int wb = (n_in >= 15) ? 5 : 4;
    const float* Wg    = (const float*)d_in[wb + 0];
    const float* bg    = (const float*)d_in[wb + 1];
    const float* Wt    = (const float*)d_in[wb + 2];
    const float* bt    = (const float*)d_in[wb + 3];
    const float* gamma = (const float*)d_in[wb + 4];
    const float* beta  = (const float*)d_in[wb + 5];
    const float* W1    = (const float*)d_in[wb + 6];
    const float* b1    = (const float*)d_in[wb + 7];
    const float* W2    = (const float*)d_in[wb + 8];
    const float* b2    = (const float*)d_in[wb + 9];

    cudaFuncSetAttribute(node_kernel, cudaFuncAttributeMaxDynamicSharedMemorySize, SMEM_DYN);

    prep_kernel<<<(Nt * Kt) / 256, 256>>>(Wg, Wt);   // also zeroes g_readout
    node_kernel<<<Nn / Mt, NTHR, SMEM_DYN>>>(xinit, xfin, gid, bg, bt);
    stats_kernel<<<CpA, 256>>>(aux, gamma, beta);
    mlp1_kernel<<<dim3(NGg / 32, Gg / 32), 256>>>(aux, W1, b1);
    mlp2_kernel<<<NGg / 8, 256>>>(W2, b2, (float*)d_out);
}

// round 17
// speedup vs baseline: 1.0272x; 1.0272x over previous
#include <cuda_runtime.h>
#include <cuda_bf16.h>
#include <cuda_fp16.h>
#include <cstdint>

// Problem constants
#define Nn   400000
#define Hh   256
#define Cc   128
#define Aa   32
#define Gg   512
#define NGg  1024
#define CpA  (Cc + Aa)          // 160
#define BN_EPS 1e-5f

#define Kt   512                // concat K: [init | fin]
#define Nt   256                // outputs: [gate(128) | t(128)]
#define Mt   64                 // nodes per block (2 CTAs/SM)
#define KC   64                 // K chunk
#define AROW (KC + 8)           // padded smem row, elems (72)
#define NTHR 256                // 8 warps: 2 row-groups x 4 col-groups

// ---------------- scratch (no allocations allowed) ----------------
__device__ float g_readout[NGg * Cc];            // segment sums  [1024,128]
__device__ float g_scale[CpA];
__device__ float g_shift[CpA];
__device__ float g_hidden[NGg * Gg];
__device__ __align__(16) __half g_Bh[Nt * Kt];   // combined weights [n][k], fp16

// ---------------- PTX helpers ----------------
__device__ __forceinline__ uint32_t smem_u32(const void* p) {
    uint32_t a;
    asm("{ .reg .u64 t; cvta.to.shared.u64 t, %1; cvt.u32.u64 %0, t; }" : "=r"(a) : "l"(p));
    return a;
}
#define LDSM4(r, addr)                                                        \
    asm volatile("ldmatrix.sync.aligned.m8n8.x4.shared.b16 {%0,%1,%2,%3}, [%4];" \
        : "=r"((r)[0]), "=r"((r)[1]), "=r"((r)[2]), "=r"((r)[3]) : "r"(addr))

#define MMA(d, a, b0, b1)                                                     \
    asm volatile("mma.sync.aligned.m16n8k16.row.col.f32.f16.f16.f32 "         \
        "{%0,%1,%2,%3},{%4,%5,%6,%7},{%8,%9},{%0,%1,%2,%3};"                  \
        : "+f"((d)[0]), "+f"((d)[1]), "+f"((d)[2]), "+f"((d)[3])              \
        : "r"((a)[0]), "r"((a)[1]), "r"((a)[2]), "r"((a)[3]), "r"(b0), "r"(b1))

#define CP16(dst, src)                                                        \
    asm volatile("cp.async.cg.shared.global [%0], [%1], 16;" :: "r"(dst), "l"(src) : "memory")
#define CP_COMMIT() asm volatile("cp.async.commit_group;" ::: "memory")
#define CP_WAIT0()  asm volatile("cp.async.wait_group 0;" ::: "memory")

// ---------------- packed f32x2 helpers (MLP tail kernels) ----------------
__device__ __forceinline__ unsigned long long pack2(float lo, float hi) {
    unsigned long long r;
    asm("mov.b64 %0, {%1, %2};" : "=l"(r) : "f"(lo), "f"(hi));
    return r;
}
__device__ __forceinline__ void unpack2(unsigned long long v, float& lo, float& hi) {
    asm("mov.b64 {%0, %1}, %2;" : "=f"(lo), "=f"(hi) : "l"(v));
}
__device__ __forceinline__ unsigned long long fma2(unsigned long long a,
                                                   unsigned long long b,
                                                   unsigned long long c) {
    unsigned long long d;
    asm("fma.rn.f32x2 %0, %1, %2, %3;" : "=l"(d) : "l"(a), "l"(b), "l"(c));
    return d;
}

// ---------------- kernel: build combined fp16 weights + zero readout ----------------
// B[n][k]: n<128 -> Wg[k][n]; n>=128 -> (k>=256 ? Wt[k-256][n-128] : 0)
__global__ void prep_kernel(const float* __restrict__ Wg, const float* __restrict__ Wt) {
    int idx = blockIdx.x * 256 + threadIdx.x;     // 0 .. 131071
    int n = idx >> 9, k = idx & 511;
    float w;
    if (n < 128)          w = Wg[(size_t)k * Cc + n];
    else if (k >= 256)    w = Wt[(size_t)(k - 256) * Cc + (n - 128)];
    else                  w = 0.0f;
    g_Bh[idx] = __float2half_rn(w);
    g_readout[idx] = 0.0f;
}

// ---------------- node kernel: HMMA GEMM + gate + segment-sum ----------------
// dynamic smem, 2 stages of:
//   A [64][72] fp16 (9216B) | B [256][72] fp16 (36864B)   = 46080B/stage
// 92160B/CTA -> 2 CTAs per SM
#define OFF_B     9216
#define STG       46080
#define SMEM_DYN  (2 * STG)      // 92160
#define OUTROW    132            // fp32 out tile row stride (elems)

__device__ __forceinline__ void ldgA(const float* __restrict__ X, int nodeBase,
                                     int kloc, int tid, float4* aR) {
#pragma unroll
    for (int it = 0; it < 4; ++it) {
        int f = tid + it * NTHR;
        int m = f >> 4, q = f & 15;
        aR[it] = *(const float4*)(X + (size_t)(nodeBase + m) * Hh + kloc + 4 * q);
    }
}

__device__ __forceinline__ void stsA(char* stage, int tid, const float4* aR) {
#pragma unroll
    for (int it = 0; it < 4; ++it) {
        int f = tid + it * NTHR;
        int m = f >> 4, q = f & 15;
        float4 v = aR[it];
        __half2 h0 = __floats2half2_rn(v.x, v.y);
        __half2 h1 = __floats2half2_rn(v.z, v.w);
        uint32_t off = m * (AROW * 2) + q * 8;
        uint2 H; H.x = *(uint32_t*)&h0; H.y = *(uint32_t*)&h1;
        *(uint2*)(stage + off) = H;
    }
}

// copy B rows [0, nrows) for one K chunk; nrows is 128 (gate-only) or 256
__device__ __forceinline__ void cpB(uint32_t stB, int kbytes, int tid, int nrows) {
    const int iters = nrows >> 5;                // 4 or 8
    for (int it = 0; it < iters; ++it) {
        int f = tid + it * NTHR;
        int n = f >> 3, q = f & 7;
        uint32_t dst = n * (AROW * 2) + q * 16;
        CP16(stB + dst, (const char*)g_Bh + (size_t)n * (Kt * 2) + kbytes + q * 16);
    }
    CP_COMMIT();
}

__global__ __launch_bounds__(NTHR, 2)
void node_kernel(const float* __restrict__ xinit, const float* __restrict__ xfin,
                 const int* __restrict__ gids,
                 const float* __restrict__ bg, const float* __restrict__ bt) {
    extern __shared__ char smem[];
    __shared__ int s_gid[Mt];
    const uint32_t sbase = smem_u32(smem);
    const int tid = threadIdx.x;
    const int wid = tid >> 5;
    const int l = tid & 31;
    const int wm = wid & 1;          // 0..1 -> 32 rows each
    const int wn = wid >> 1;         // 0..3 -> 32-col gate slice AND 32-col t slice
    const int nodeBase = blockIdx.x * Mt;

    if (tid < Mt) s_gid[tid] = gids[nodeBase + tid];

    // ldmatrix per-thread offsets (bytes)
    const uint32_t aOff = ((wm * 32 + (l & 15)) * AROW + ((l >> 4) * 8)) * 2;
    // B col-slice bases: gate slice at cols [wn*32, wn*32+32),
    //                    t slice at cols [128 + wn*32, 128 + wn*32 + 32)
    const uint32_t bRowSel = (((l >> 4) & 1) * 8 + (l & 7));
    const uint32_t bKSel = ((l >> 3) & 1) * 8;
    const uint32_t bOffG = ((wn * 32 + bRowSel) * AROW + bKSel) * 2 + OFF_B;
    const uint32_t bOffT = (((128 + wn * 32) + bRowSel) * AROW + bKSel) * 2 + OFF_B;

    float accG[2][4][4];             // gate: [mt 16-row][nt 8-col][frag]
    float accT[2][4][4];             // t
#pragma unroll
    for (int i = 0; i < 2; i++)
#pragma unroll
        for (int j = 0; j < 4; j++)
#pragma unroll
            for (int p = 0; p < 4; p++) { accG[i][j][p] = 0.0f; accT[i][j][p] = 0.0f; }

    float4 rA[4];

    // prologue: chunk 0 staged (init half, gate-only B rows)
    ldgA(xinit, nodeBase, 0, tid, rA);
    cpB(sbase + OFF_B, 0, tid, 128);
    stsA(smem, tid, rA);
    CP_WAIT0();
    __syncthreads();

    for (int j = 0; j < 8; ++j) {
        const uint32_t stg = sbase + (uint32_t)(j & 1) * STG;
        // prefetch chunk j+1 into the other stage
        if (j + 1 < 8) {
            const int c = j + 1;
            cpB(sbase + (uint32_t)(c & 1) * STG + OFF_B, c * KC * 2, tid,
                (c < 4) ? 128 : 256);
            const float* X = (c < 4) ? xinit : xfin;
            ldgA(X, nodeBase, (c & 3) * KC, tid, rA);
        }

        // all 8 warps: 32-col gate slice every chunk; 32-col t slice on chunks 4-7
        const bool doT = (j >= 4);
#pragma unroll
        for (int ks = 0; ks < 4; ++ks) {
            const uint32_t aA = stg + aOff + ks * 32;
            uint32_t ah0[4], ah1[4];
            LDSM4(ah0, aA);
            LDSM4(ah1, aA + 16 * AROW * 2);
#pragma unroll
            for (int np = 0; np < 2; ++np) {
                const uint32_t bA = stg + bOffG + np * (16 * AROW * 2) + ks * 32;
                uint32_t bh[4];
                LDSM4(bh, bA);
                MMA(accG[0][2 * np],     ah0, bh[0], bh[1]);
                MMA(accG[0][2 * np + 1], ah0, bh[2], bh[3]);
                MMA(accG[1][2 * np],     ah1, bh[0], bh[1]);
                MMA(accG[1][2 * np + 1], ah1, bh[2], bh[3]);
            }
            if (doT) {
#pragma unroll
                for (int np = 0; np < 2; ++np) {
                    const uint32_t bA = stg + bOffT + np * (16 * AROW * 2) + ks * 32;
                    uint32_t bh[4];
                    LDSM4(bh, bA);
                    MMA(accT[0][2 * np],     ah0, bh[0], bh[1]);
                    MMA(accT[0][2 * np + 1], ah0, bh[2], bh[3]);
                    MMA(accT[1][2 * np],     ah1, bh[0], bh[1]);
                    MMA(accT[1][2 * np + 1], ah1, bh[2], bh[3]);
                }
            }
        }

        // STS chunk j+1 (LDG'd at top of this iteration -> full MMA block of slack)
        if (j + 1 < 8) {
            stsA(smem + ((j + 1) & 1) * STG, tid, rA);
            CP_WAIT0();
        }
        __syncthreads();
    }

    // ---- epilogue: each warp owns matching gate & t columns -> no exchange ----
    float* sOut = (float*)smem;          // [64][OUTROW] fp32, aliases stages
    const int r = l >> 2;
    const int cq = (l & 3) * 2;

#pragma unroll
    for (int mt = 0; mt < 2; ++mt)
#pragma unroll
        for (int nt = 0; nt < 4; ++nt) {
            int m = wm * 32 + mt * 16 + r;
            int c = wn * 32 + nt * 8 + cq;
            float bg0 = bg[c], bg1 = bg[c + 1];
            float bt0 = bt[c], bt1 = bt[c + 1];
            float* p = sOut + m * OUTROW + c;
            p[0] = (accT[mt][nt][0] + bt0) / (1.0f + __expf(-(accG[mt][nt][0] + bg0)));
            p[1] = (accT[mt][nt][1] + bt1) / (1.0f + __expf(-(accG[mt][nt][1] + bg1)));
            p[8 * OUTROW]     = (accT[mt][nt][2] + bt0) / (1.0f + __expf(-(accG[mt][nt][2] + bg0)));
            p[8 * OUTROW + 1] = (accT[mt][nt][3] + bt1) / (1.0f + __expf(-(accG[mt][nt][3] + bg1)));
        }
    __syncthreads();

    // sorted-id run-length segment sum: 2 threads per channel, 32 nodes each
    {
        const int c = tid & 127;
        const int n0 = (tid >> 7) * 32;
        float run = 0.0f;
        int cur = s_gid[n0];
        for (int n = n0; n < n0 + 32; ++n) {
            int g = s_gid[n];
            if (g != cur) {
                atomicAdd(&g_readout[(size_t)cur * Cc + c], run);
                run = 0.0f; cur = g;
            }
            run += sOut[n * OUTROW + c];
        }
        atomicAdd(&g_readout[(size_t)cur * Cc + c], run);
    }
}

// ---------------- kernel: per-column BN stats -> scale/shift ----------------
__global__ __launch_bounds__(256)
void stats_kernel(const float* __restrict__ aux,
                  const float* __restrict__ gamma, const float* __restrict__ beta) {
    const int j = blockIdx.x;
    const int tid = threadIdx.x;
    float s = 0.0f, sq = 0.0f;
    for (int g = tid; g < NGg; g += 256) {
        float v = (j < Cc) ? g_readout[(size_t)g * Cc + j]
                           : aux[(size_t)g * Aa + (j - Cc)];
        s += v; sq += v * v;
    }
#pragma unroll
    for (int o = 16; o; o >>= 1) {
        s  += __shfl_xor_sync(0xffffffffu, s,  o);
        sq += __shfl_xor_sync(0xffffffffu, sq, o);
    }
    __shared__ float ws[8], wq[8];
    if ((tid & 31) == 0) { ws[tid >> 5] = s; wq[tid >> 5] = sq; }
    __syncthreads();
    if (tid == 0) {
        float S = 0.0f, Q = 0.0f;
#pragma unroll
        for (int i = 0; i < 8; i++) { S += ws[i]; Q += wq[i]; }
        float mean = S * (1.0f / NGg);
        float var  = Q * (1.0f / NGg) - mean * mean;
        float sc = gamma[j] * rsqrtf(var + BN_EPS);
        g_scale[j] = sc;
        g_shift[j] = beta[j] - mean * sc;
    }
}

// ---------------- kernel: hidden = relu(norm @ W1 + b1) ----------------
// 32x64 tile, grid (NGg/32, Gg/64) = (32, 8) = 256 CTAs (R13 measured optimum)
__global__ __launch_bounds__(256)
void mlp1_kernel(const float* __restrict__ aux,
                 const float* __restrict__ W1, const float* __restrict__ b1) {
    __shared__ float sA[32][33];
    __shared__ float sB[32][64];
    const int tid = threadIdx.x;
    const int tm = tid >> 4, tc = tid & 15;     // 16x16 thread grid
    const int c0 = tc * 4;
    const int rowBase = blockIdx.x * 32;
    const int colBase = blockIdx.y * 64;

    unsigned long long acc[2][2];
#pragma unroll
    for (int i = 0; i < 2; i++)
#pragma unroll
        for (int j = 0; j < 2; j++) acc[i][j] = 0ULL;

    for (int chunk = 0; chunk < 5; ++chunk) {       // K = 160
        const int k0 = chunk * 32;
        __syncthreads();
        {   // A tile 32x32, normalized on load: 256 float4 = 256 threads
            int n = tid >> 3, q = tid & 7;
            int j = k0 + 4 * q;
            float4 v;
            if (j < Cc) v = *(const float4*)(g_readout + (size_t)(rowBase + n) * Cc + j);
            else        v = *(const float4*)(aux + (size_t)(rowBase + n) * Aa + (j - Cc));
            float4 sc = *(const float4*)(g_scale + j);
            float4 sh = *(const float4*)(g_shift + j);
            sA[n][4 * q + 0] = fmaf(v.x, sc.x, sh.x);
            sA[n][4 * q + 1] = fmaf(v.y, sc.y, sh.y);
            sA[n][4 * q + 2] = fmaf(v.z, sc.z, sh.z);
            sA[n][4 * q + 3] = fmaf(v.w, sc.w, sh.w);
        }
#pragma unroll
        for (int it = 0; it < 2; ++it) {            // B tile 32x64 = 512 float4
            int f = tid + it * 256;
            int k = f >> 4, c4 = (f & 15) * 4;
            *(float4*)&sB[k][c4] = *(const float4*)(W1 + (size_t)(k0 + k) * Gg + colBase + c4);
        }
        __syncthreads();
#pragma unroll 8
        for (int k = 0; k < 32; ++k) {
            unsigned long long av[2];
#pragma unroll
            for (int i = 0; i < 2; i++) { float a = sA[tm * 2 + i][k]; av[i] = pack2(a, a); }
            ulonglong2 w = *(const ulonglong2*)&sB[k][c0];
#pragma unroll
            for (int i = 0; i < 2; i++) {
                acc[i][0] = fma2(av[i], w.x, acc[i][0]);
                acc[i][1] = fma2(av[i], w.y, acc[i][1]);
            }
        }
    }
    float bv[4];
#pragma unroll
    for (int j = 0; j < 4; j++) bv[j] = b1[colBase + c0 + j];
#pragma unroll
    for (int i = 0; i < 2; i++) {
        int r = rowBase + tm * 2 + i;
#pragma unroll
        for (int j = 0; j < 2; j++) {
            float lo, hi; unpack2(acc[i][j], lo, hi);
            lo = fmaxf(lo + bv[2 * j], 0.0f);
            hi = fmaxf(hi + bv[2 * j + 1], 0.0f);
            g_hidden[(size_t)r * Gg + colBase + c0 + 2 * j]     = lo;
            g_hidden[(size_t)r * Gg + colBase + c0 + 2 * j + 1] = hi;
        }
    }
}

// ---------------- kernel: logits = hidden @ W2 + b2 ----------------
// 8-row x 64-col tile, grid (NGg/8, 2) = 256 CTAs
// sB row stride 68 floats = 272B = 16*17 -> float4 stores aligned
__global__ __launch_bounds__(256)
void mlp2_kernel(const float* __restrict__ W2, const float* __restrict__ b2,
                 float* __restrict__ out) {
    __shared__ float sA[8][65];
    __shared__ float sB[64][68];
    const int tid = threadIdx.x;
    const int tm = tid >> 5, tc = tid & 31;     // 8 rows x 32 col-groups of 2
    const int c0 = tc * 2;
    const int rowBase = blockIdx.x * 8;
    const int colBase = blockIdx.y * 64;

    unsigned long long acc = 0ULL;
    for (int chunk = 0; chunk < 8; ++chunk) {       // K = 512
        const int k0 = chunk * 64;
        __syncthreads();
        if (tid < 128) {                            // A tile 8x64 = 128 float4
            int n = tid >> 4, q = tid & 15;
            float4 v = *(const float4*)(g_hidden + (size_t)(rowBase + n) * Gg + k0 + 4 * q);
            sA[n][4 * q + 0] = v.x; sA[n][4 * q + 1] = v.y;
            sA[n][4 * q + 2] = v.z; sA[n][4 * q + 3] = v.w;
        }
#pragma unroll
        for (int it = 0; it < 4; ++it) {            // B tile 64x64 = 1024 float4
            int f = tid + it * 256;
            int k = f >> 4, c4 = (f & 15) * 4;
            *(float4*)&sB[k][c4] = *(const float4*)(W2 + (size_t)(k0 + k) * Cc + colBase + c4);
        }
        __syncthreads();
#pragma unroll 8
        for (int k = 0; k < 64; ++k) {
            float a = sA[tm][k];
            unsigned long long w = *(const unsigned long long*)&sB[k][c0];
            acc = fma2(pack2(a, a), w, acc);
        }
    }
    float lo, hi; unpack2(acc, lo, hi);
    int r = rowBase + tm;
    out[(size_t)r * Cc + colBase + c0]     = lo + b2[colBase + c0];
    out[(size_t)r * Cc + colBase + c0 + 1] = hi + b2[colBase + c0 + 1];
}

// ---------------- launch ----------------
extern "C" void kernel_launch(void* const* d_in, const int* in_sizes, int n_in,
                              void* d_out, int out_size) {
    (void)in_sizes; (void)out_size;
    const float* xinit = (const float*)d_in[0];
    const float* xfin  = (const float*)d_in[1];
    const float* aux   = (const float*)d_in[2];
    const int*   gid   = (const int*)d_in[3];
    const int wb = (n_in >= 15) ? 5 : 4;
    const float* Wg    = (const float*)d_in[wb + 0];
    const float* bg    = (const float*)d_in[wb + 1];
    const float* Wt    = (const float*)d_in[wb + 2];
    const float* bt    = (const float*)d_in[wb + 3];
    const float* gamma = (const float*)d_in[wb + 4];
    const float* beta  = (const float*)d_in[wb + 5];
    const float* W1    = (const float*)d_in[wb + 6];
    const float* b1    = (const float*)d_in[wb + 7];
    const float* W2    = (const float*)d_in[wb + 8];
    const float* b2    = (const float*)d_in[wb + 9];

    cudaFuncSetAttribute(node_kernel, cudaFuncAttributeMaxDynamicSharedMemorySize, SMEM_DYN);

    prep_kernel<<<(Nt * Kt) / 256, 256>>>(Wg, Wt);   // also zeroes g_readout
    node_kernel<<<Nn / Mt, NTHR, SMEM_DYN>>>(xinit, xfin, gid, bg, bt);
    stats_kernel<<<CpA, 256>>>(aux, gamma, beta);
    mlp1_kernel<<<dim3(NGg / 32, Gg / 64), 256>>>(aux, W1, b1);
    mlp2_kernel<<<dim3(NGg / 8, 2), 256>>>(W2, b2, (float*)d_out);
}